// round 3
// baseline (speedup 1.0000x reference)
#include <cuda_runtime.h>
#include <math.h>

#define NFEAT 16
#define EFEAT 8
#define HC    256
#define NCLS  4

static const int MAXN = 50000;
static const int MAXE = 800000;

typedef unsigned long long u64;

__device__ __forceinline__ u64 pack2(float a, float b) {
    u64 r; asm("mov.b64 %0, {%1, %2};" : "=l"(r) : "f"(a), "f"(b)); return r;
}
__device__ __forceinline__ float2 unpack2(u64 v) {
    float2 f; asm("mov.b64 {%0, %1}, %2;" : "=f"(f.x), "=f"(f.y) : "l"(v)); return f;
}
__device__ __forceinline__ u64 fma2(u64 a, u64 b, u64 c) {
    u64 d; asm("fma.rn.f32x2 %0, %1, %2, %3;" : "=l"(d) : "l"(a), "l"(b), "l"(c)); return d;
}

// ---------------- scratch ----------------
__device__ float g_x1  [MAXN * 64];
__device__ float g_q   [MAXN * HC];
__device__ float g_k   [MAXN * HC];
__device__ float g_v   [MAXN * HC];
__device__ float g_skip[MAXN * HC];
__device__ float g_g   [MAXN * HC];
__device__ float g_qb  [MAXN * 4];
__device__ float g_e   [MAXE * 64];
__device__ float g_outv[MAXN * HC];
__device__ float g_t   [MAXN * HC];
__device__ float g_suma[MAXN * 4];
__device__ float g_act [MAXN * HC];
__device__ float g_wtt [HC * 64];     // wedge transposed: wtt[cglob][ii]
__device__ int   g_deg [MAXN];
__device__ int   g_rowptr[MAXN + 1];
__device__ int   g_cursor[MAXN];
__device__ int   g_eid [MAXE];
__device__ int   g_src [MAXE];

// ---------------- CSR build ----------------
__global__ void k_zero_deg(int n) {
    int i = blockIdx.x * blockDim.x + threadIdx.x;
    if (i < n) g_deg[i] = 0;
}
__global__ void k_hist(const int* __restrict__ ei, int e) {
    int i = blockIdx.x * blockDim.x + threadIdx.x;
    if (i < e) atomicAdd(&g_deg[ei[e + i]], 1);
}
__global__ void k_scan(int n) {
    __shared__ int sh[1024];
    __shared__ int s_off;
    int tid = threadIdx.x;
    if (tid == 0) { s_off = 0; g_rowptr[0] = 0; }
    __syncthreads();
    for (int base = 0; base < n; base += 1024) {
        int i = base + tid;
        int val = (i < n) ? g_deg[i] : 0;
        sh[tid] = val;
        __syncthreads();
        for (int off = 1; off < 1024; off <<= 1) {
            int y = (tid >= off) ? sh[tid - off] : 0;
            __syncthreads();
            sh[tid] += y;
            __syncthreads();
        }
        int incl = sh[tid];
        if (i < n) {
            g_rowptr[i + 1] = s_off + incl;
            g_cursor[i]     = s_off + incl - val;
        }
        __syncthreads();
        if (tid == 0) s_off += sh[1023];
        __syncthreads();
    }
}
__global__ void k_scatter(const int* __restrict__ ei, int e) {
    int i = blockIdx.x * blockDim.x + threadIdx.x;
    if (i < e) {
        int dst = ei[e + i];
        int pos = atomicAdd(&g_cursor[dst], 1);
        g_eid[pos] = i;
        g_src[pos] = ei[i];
    }
}

// ---------------- wedge transpose (one-time tiny) ----------------
__global__ void k_wtt(const float* __restrict__ wedge) {
    int idx = blockIdx.x * 256 + threadIdx.x;     // 64 blocks -> 16384
    int cg = idx >> 6, ii = idx & 63;
    g_wtt[cg * 64 + ii] = wedge[ii * HC + cg];
}

// ---------------- node embed ----------------
__global__ void k_node_embed(const float* __restrict__ x,
                             const float* __restrict__ w00,
                             const float* __restrict__ b00, int n) {
    __shared__ float ws[NFEAT * 64];
    __shared__ float xs[64][NFEAT];
    int tid = threadIdx.x;
    for (int i = tid; i < NFEAT * 64; i += 256) ws[i] = w00[i];
    int nb = blockIdx.x * 64;
    for (int i = tid; i < 64 * NFEAT; i += 256) {
        int nn = nb + i / NFEAT;
        xs[i / NFEAT][i % NFEAT] = (nn < n) ? x[nn * NFEAT + (i % NFEAT)] : 0.f;
    }
    __syncthreads();
    int ln = tid >> 2;
    int node = nb + ln;
    int c0 = (tid & 3) * 16;
    if (node < n) {
        #pragma unroll
        for (int j = 0; j < 16; j++) {
            float acc = __ldg(&b00[c0 + j]);
            #pragma unroll
            for (int i = 0; i < NFEAT; i++) acc += xs[ln][i] * ws[i * 64 + c0 + j];
            g_x1[node * 64 + c0 + j] = fmaxf(acc, 0.f);
        }
    }
}

// ---------------- fused projections (grid.y selects matrix) ----------------
__global__ void k_proj(const float* __restrict__ W0, const float* __restrict__ B0,
                       const float* __restrict__ W1, const float* __restrict__ B1,
                       const float* __restrict__ W2, const float* __restrict__ B2,
                       const float* __restrict__ W3, const float* __restrict__ B3,
                       int n) {
    int sel = blockIdx.y;
    const float* W = (sel == 0) ? W0 : (sel == 1) ? W1 : (sel == 2) ? W2 : W3;
    const float* B = (sel == 0) ? B0 : (sel == 1) ? B1 : (sel == 2) ? B2 : B3;
    float* out = (sel == 0) ? g_q : (sel == 1) ? g_k : (sel == 2) ? g_v : g_skip;

    __shared__ float xs[32 * 64];
    int tid = threadIdx.x;
    int nb = blockIdx.x * 32;
    for (int i = tid; i < 512; i += 256) {
        int row = i >> 4, q4 = i & 15;
        int node = nb + row;
        float4 v = make_float4(0.f, 0.f, 0.f, 0.f);
        if (node < n) v = *(const float4*)&g_x1[node * 64 + q4 * 4];
        *(float4*)&xs[row * 64 + q4 * 4] = v;
    }
    __syncthreads();

    int warp = tid >> 5, lane = tid & 31;
    int row0 = (warp >> 2) * 16 + (lane >> 3) * 4;
    int col0 = (warp & 3) * 64 + (lane & 7) * 8;

    u64 acc[4][4];
    #pragma unroll
    for (int jj = 0; jj < 4; jj++) {
        u64 b = pack2(__ldg(&B[col0 + jj * 2]), __ldg(&B[col0 + jj * 2 + 1]));
        #pragma unroll
        for (int rr = 0; rr < 4; rr++) acc[rr][jj] = b;
    }
    for (int i4 = 0; i4 < 64; i4 += 4) {
        float4 xv[4];
        #pragma unroll
        for (int rr = 0; rr < 4; rr++) xv[rr] = *(const float4*)&xs[(row0 + rr) * 64 + i4];
        #pragma unroll
        for (int ii = 0; ii < 4; ii++) {
            const float* wrow = &W[(i4 + ii) * HC + col0];
            ulonglong2 wa = *(const ulonglong2*)wrow;
            ulonglong2 wb = *(const ulonglong2*)(wrow + 4);
            #pragma unroll
            for (int rr = 0; rr < 4; rr++) {
                float h = (ii == 0) ? xv[rr].x : (ii == 1) ? xv[rr].y : (ii == 2) ? xv[rr].z : xv[rr].w;
                u64 hh = pack2(h, h);
                acc[rr][0] = fma2(hh, wa.x, acc[rr][0]);
                acc[rr][1] = fma2(hh, wa.y, acc[rr][1]);
                acc[rr][2] = fma2(hh, wb.x, acc[rr][2]);
                acc[rr][3] = fma2(hh, wb.y, acc[rr][3]);
            }
        }
    }
    #pragma unroll
    for (int rr = 0; rr < 4; rr++) {
        int node = nb + row0 + rr;
        if (node < n) {
            #pragma unroll
            for (int jj = 0; jj < 4; jj++) {
                float2 f = unpack2(acc[rr][jj]);
                *(float2*)&out[node * HC + col0 + jj * 2] = f;
            }
        }
    }
}

// ---------------- g = per-head wedge^T @ q ; qb = q . bedge ----------------
__global__ void k_g(const float* __restrict__ bedge, int n) {
    __shared__ float qs[32 * HC];   // 32KB
    int tid = threadIdx.x;
    int nb = blockIdx.x * 32;
    for (int i = tid; i < 2048; i += 256) {
        int row = i >> 6, q4 = i & 63;
        int node = nb + row;
        float4 v = make_float4(0.f, 0.f, 0.f, 0.f);
        if (node < n) v = *(const float4*)&g_q[node * HC + q4 * 4];
        *(float4*)&qs[row * HC + q4 * 4] = v;
    }
    __syncthreads();

    int warp = tid >> 5, lane = tid & 31;
    int row0 = (warp >> 2) * 16 + (lane >> 3) * 4;
    int h    = warp & 3;
    int ii0  = (lane & 7) * 8;
    int col0 = h * 64 + ii0;

    u64 acc[4][4];
    #pragma unroll
    for (int rr = 0; rr < 4; rr++)
        #pragma unroll
        for (int jj = 0; jj < 4; jj++) acc[rr][jj] = 0ull;

    for (int c4 = 0; c4 < 64; c4 += 4) {
        float4 qv[4];
        #pragma unroll
        for (int rr = 0; rr < 4; rr++) qv[rr] = *(const float4*)&qs[(row0 + rr) * HC + h * 64 + c4];
        #pragma unroll
        for (int ci = 0; ci < 4; ci++) {
            const float* wrow = &g_wtt[(h * 64 + c4 + ci) * 64 + ii0];
            ulonglong2 wa = *(const ulonglong2*)wrow;
            ulonglong2 wb = *(const ulonglong2*)(wrow + 4);
            #pragma unroll
            for (int rr = 0; rr < 4; rr++) {
                float q = (ci == 0) ? qv[rr].x : (ci == 1) ? qv[rr].y : (ci == 2) ? qv[rr].z : qv[rr].w;
                u64 hh = pack2(q, q);
                acc[rr][0] = fma2(hh, wa.x, acc[rr][0]);
                acc[rr][1] = fma2(hh, wa.y, acc[rr][1]);
                acc[rr][2] = fma2(hh, wb.x, acc[rr][2]);
                acc[rr][3] = fma2(hh, wb.y, acc[rr][3]);
            }
        }
    }
    #pragma unroll
    for (int rr = 0; rr < 4; rr++) {
        int node = nb + row0 + rr;
        if (node < n) {
            #pragma unroll
            for (int jj = 0; jj < 4; jj++) {
                float2 f = unpack2(acc[rr][jj]);
                *(float2*)&g_g[node * HC + col0 + jj * 2] = f;
            }
        }
    }
    // qb
    if (tid < 128) {
        int m = tid >> 2, h2 = tid & 3;
        int node = nb + m;
        if (node < n) {
            float s = 0.f;
            for (int c = 0; c < 64; c++) s += qs[m * HC + h2 * 64 + c] * __ldg(&bedge[h2 * 64 + c]);
            g_qb[node * 4 + h2] = s;
        }
    }
}

// ---------------- edge MLP: 128-edge tiles, f32x2, dynamic smem -----------
__global__ void k_edgemlp(const float* __restrict__ eattr,
                          const float* __restrict__ we1, const float* __restrict__ be1,
                          const float* __restrict__ we2, const float* __restrict__ be2,
                          const float* __restrict__ we3, const float* __restrict__ be3,
                          int e) {
    extern __shared__ float sm[];
    float* w1s = sm;                // 512
    float* w2s = sm + 512;          // 4096
    float* w3s = sm + 4608;         // 4096
    float* es  = sm + 8704;         // 1024
    float* h1  = sm + 9728;         // 8192
    float* h2  = sm + 17920;        // 8192
    int*   eids = (int*)(sm + 26112); // 128 ints

    int tid = threadIdx.x;
    int pb = blockIdx.x * 128;
    for (int i = tid; i < 512; i += 256) w1s[i] = we1[i];
    for (int i = tid; i < 4096; i += 256) { w2s[i] = we2[i]; w3s[i] = we3[i]; }
    if (tid < 128) eids[tid] = (pb + tid < e) ? g_eid[pb + tid] : -1;
    __syncthreads();
    {
        int row = tid >> 1, half = tid & 1;
        int id = eids[row];
        float4 v = make_float4(0.f, 0.f, 0.f, 0.f);
        if (id >= 0) v = *(const float4*)&eattr[id * 8 + half * 4];
        *(float4*)&es[row * 8 + half * 4] = v;
    }
    __syncthreads();

    int col0 = (tid & 7) * 8;
    int row0 = (tid >> 3) * 4;

    // ---- layer 1 (8 -> 64) ----
    {
        u64 acc[4][4];
        #pragma unroll
        for (int jj = 0; jj < 4; jj++) {
            u64 b = pack2(__ldg(&be1[col0 + jj * 2]), __ldg(&be1[col0 + jj * 2 + 1]));
            #pragma unroll
            for (int rr = 0; rr < 4; rr++) acc[rr][jj] = b;
        }
        #pragma unroll
        for (int i = 0; i < 8; i++) {
            ulonglong2 wa = *(const ulonglong2*)&w1s[i * 64 + col0];
            ulonglong2 wb = *(const ulonglong2*)&w1s[i * 64 + col0 + 4];
            #pragma unroll
            for (int rr = 0; rr < 4; rr++) {
                float hv = es[(row0 + rr) * 8 + i];
                u64 hh = pack2(hv, hv);
                acc[rr][0] = fma2(hh, wa.x, acc[rr][0]);
                acc[rr][1] = fma2(hh, wa.y, acc[rr][1]);
                acc[rr][2] = fma2(hh, wb.x, acc[rr][2]);
                acc[rr][3] = fma2(hh, wb.y, acc[rr][3]);
            }
        }
        #pragma unroll
        for (int rr = 0; rr < 4; rr++)
            #pragma unroll
            for (int jj = 0; jj < 4; jj++) {
                float2 f = unpack2(acc[rr][jj]);
                *(float2*)&h1[(row0 + rr) * 64 + col0 + jj * 2] =
                    make_float2(fmaxf(f.x, 0.f), fmaxf(f.y, 0.f));
            }
    }
    __syncthreads();

    // ---- layer 2 (64 -> 64) ----
    {
        u64 acc[4][4];
        #pragma unroll
        for (int jj = 0; jj < 4; jj++) {
            u64 b = pack2(__ldg(&be2[col0 + jj * 2]), __ldg(&be2[col0 + jj * 2 + 1]));
            #pragma unroll
            for (int rr = 0; rr < 4; rr++) acc[rr][jj] = b;
        }
        for (int i4 = 0; i4 < 64; i4 += 4) {
            float4 hv[4];
            #pragma unroll
            for (int rr = 0; rr < 4; rr++) hv[rr] = *(const float4*)&h1[(row0 + rr) * 64 + i4];
            #pragma unroll
            for (int ii = 0; ii < 4; ii++) {
                ulonglong2 wa = *(const ulonglong2*)&w2s[(i4 + ii) * 64 + col0];
                ulonglong2 wb = *(const ulonglong2*)&w2s[(i4 + ii) * 64 + col0 + 4];
                #pragma unroll
                for (int rr = 0; rr < 4; rr++) {
                    float h = (ii == 0) ? hv[rr].x : (ii == 1) ? hv[rr].y : (ii == 2) ? hv[rr].z : hv[rr].w;
                    u64 hh = pack2(h, h);
                    acc[rr][0] = fma2(hh, wa.x, acc[rr][0]);
                    acc[rr][1] = fma2(hh, wa.y, acc[rr][1]);
                    acc[rr][2] = fma2(hh, wb.x, acc[rr][2]);
                    acc[rr][3] = fma2(hh, wb.y, acc[rr][3]);
                }
            }
        }
        __syncthreads();
        #pragma unroll
        for (int rr = 0; rr < 4; rr++)
            #pragma unroll
            for (int jj = 0; jj < 4; jj++) {
                float2 f = unpack2(acc[rr][jj]);
                *(float2*)&h2[(row0 + rr) * 64 + col0 + jj * 2] =
                    make_float2(fmaxf(f.x, 0.f), fmaxf(f.y, 0.f));
            }
    }
    __syncthreads();

    // ---- layer 3 (64 -> 64) -> g_e ----
    {
        u64 acc[4][4];
        #pragma unroll
        for (int jj = 0; jj < 4; jj++) {
            u64 b = pack2(__ldg(&be3[col0 + jj * 2]), __ldg(&be3[col0 + jj * 2 + 1]));
            #pragma unroll
            for (int rr = 0; rr < 4; rr++) acc[rr][jj] = b;
        }
        for (int i4 = 0; i4 < 64; i4 += 4) {
            float4 hv[4];
            #pragma unroll
            for (int rr = 0; rr < 4; rr++) hv[rr] = *(const float4*)&h2[(row0 + rr) * 64 + i4];
            #pragma unroll
            for (int ii = 0; ii < 4; ii++) {
                ulonglong2 wa = *(const ulonglong2*)&w3s[(i4 + ii) * 64 + col0];
                ulonglong2 wb = *(const ulonglong2*)&w3s[(i4 + ii) * 64 + col0 + 4];
                #pragma unroll
                for (int rr = 0; rr < 4; rr++) {
                    float h = (ii == 0) ? hv[rr].x : (ii == 1) ? hv[rr].y : (ii == 2) ? hv[rr].z : hv[rr].w;
                    u64 hh = pack2(h, h);
                    acc[rr][0] = fma2(hh, wa.x, acc[rr][0]);
                    acc[rr][1] = fma2(hh, wa.y, acc[rr][1]);
                    acc[rr][2] = fma2(hh, wb.x, acc[rr][2]);
                    acc[rr][3] = fma2(hh, wb.y, acc[rr][3]);
                }
            }
        }
        #pragma unroll
        for (int rr = 0; rr < 4; rr++) {
            int p = pb + row0 + rr;
            if (p < e) {
                #pragma unroll
                for (int jj = 0; jj < 4; jj++) {
                    float2 f = unpack2(acc[rr][jj]);
                    *(float2*)&g_e[p * 64 + col0 + jj * 2] =
                        make_float2(fmaxf(f.x, 0.f), fmaxf(f.y, 0.f));
                }
            }
        }
    }
}

// ---------------- attention: warp per node, 8-lane head groups -------------
__device__ __forceinline__ float dot4(float4 a, float4 b) {
    return a.x * b.x + a.y * b.y + a.z * b.z + a.w * b.w;
}

__global__ void k_attn(int n) {
    int gw = (blockIdx.x * blockDim.x + threadIdx.x) >> 5;
    int lane = threadIdx.x & 31;
    if (gw >= n) return;
    int node = gw;
    int beg = g_rowptr[node], end = g_rowptr[node + 1];

    int h = lane >> 3;
    int c8 = (lane & 7) * 8;
    int chan = h * 64 + c8;

    float4 q0 = *(const float4*)&g_q[node * HC + chan];
    float4 q1 = *(const float4*)&g_q[node * HC + chan + 4];
    float4 gg0 = *(const float4*)&g_g[node * HC + chan];
    float4 gg1 = *(const float4*)&g_g[node * HC + chan + 4];
    float qb = g_qb[node * 4 + h];

    float s = 0.f;
    float4 av0 = {0,0,0,0}, av1 = {0,0,0,0};
    float4 at0 = {0,0,0,0}, at1 = {0,0,0,0};

    int p = beg;
    for (; p + 2 <= end; p += 2) {
        int srcA = g_src[p], srcB = g_src[p + 1];
        float4 kA0 = *(const float4*)&g_k[srcA * HC + chan];
        float4 kA1 = *(const float4*)&g_k[srcA * HC + chan + 4];
        float4 eA0 = *(const float4*)&g_e[p * 64 + c8];
        float4 eA1 = *(const float4*)&g_e[p * 64 + c8 + 4];
        float4 kB0 = *(const float4*)&g_k[srcB * HC + chan];
        float4 kB1 = *(const float4*)&g_k[srcB * HC + chan + 4];
        float4 eB0 = *(const float4*)&g_e[(p + 1) * 64 + c8];
        float4 eB1 = *(const float4*)&g_e[(p + 1) * 64 + c8 + 4];

        float dA = dot4(q0, kA0) + dot4(q1, kA1) + dot4(gg0, eA0) + dot4(gg1, eA1);
        float dB = dot4(q0, kB0) + dot4(q1, kB1) + dot4(gg0, eB0) + dot4(gg1, eB1);
        dA += __shfl_xor_sync(0xffffffffu, dA, 1);
        dB += __shfl_xor_sync(0xffffffffu, dB, 1);
        dA += __shfl_xor_sync(0xffffffffu, dA, 2);
        dB += __shfl_xor_sync(0xffffffffu, dB, 2);
        dA += __shfl_xor_sync(0xffffffffu, dA, 4);
        dB += __shfl_xor_sync(0xffffffffu, dB, 4);
        float peA = __expf((dA + qb) * 0.125f);
        float peB = __expf((dB + qb) * 0.125f);
        s += peA + peB;

        float4 vA0 = *(const float4*)&g_v[srcA * HC + chan];
        float4 vA1 = *(const float4*)&g_v[srcA * HC + chan + 4];
        float4 vB0 = *(const float4*)&g_v[srcB * HC + chan];
        float4 vB1 = *(const float4*)&g_v[srcB * HC + chan + 4];

        av0.x += peA * vA0.x + peB * vB0.x;  av0.y += peA * vA0.y + peB * vB0.y;
        av0.z += peA * vA0.z + peB * vB0.z;  av0.w += peA * vA0.w + peB * vB0.w;
        av1.x += peA * vA1.x + peB * vB1.x;  av1.y += peA * vA1.y + peB * vB1.y;
        av1.z += peA * vA1.z + peB * vB1.z;  av1.w += peA * vA1.w + peB * vB1.w;
        at0.x += peA * eA0.x + peB * eB0.x;  at0.y += peA * eA0.y + peB * eB0.y;
        at0.z += peA * eA0.z + peB * eB0.z;  at0.w += peA * eA0.w + peB * eB0.w;
        at1.x += peA * eA1.x + peB * eB1.x;  at1.y += peA * eA1.y + peB * eB1.y;
        at1.z += peA * eA1.z + peB * eB1.z;  at1.w += peA * eA1.w + peB * eB1.w;
    }
    if (p < end) {
        int src = g_src[p];
        float4 k0 = *(const float4*)&g_k[src * HC + chan];
        float4 k1 = *(const float4*)&g_k[src * HC + chan + 4];
        float4 e0 = *(const float4*)&g_e[p * 64 + c8];
        float4 e1 = *(const float4*)&g_e[p * 64 + c8 + 4];
        float d = dot4(q0, k0) + dot4(q1, k1) + dot4(gg0, e0) + dot4(gg1, e1);
        d += __shfl_xor_sync(0xffffffffu, d, 1);
        d += __shfl_xor_sync(0xffffffffu, d, 2);
        d += __shfl_xor_sync(0xffffffffu, d, 4);
        float pe = __expf((d + qb) * 0.125f);
        s += pe;
        float4 v0 = *(const float4*)&g_v[src * HC + chan];
        float4 v1 = *(const float4*)&g_v[src * HC + chan + 4];
        av0.x += pe * v0.x; av0.y += pe * v0.y; av0.z += pe * v0.z; av0.w += pe * v0.w;
        av1.x += pe * v1.x; av1.y += pe * v1.y; av1.z += pe * v1.z; av1.w += pe * v1.w;
        at0.x += pe * e0.x; at0.y += pe * e0.y; at0.z += pe * e0.z; at0.w += pe * e0.w;
        at1.x += pe * e1.x; at1.y += pe * e1.y; at1.z += pe * e1.z; at1.w += pe * e1.w;
    }

    float sinv = 1.f / (s + 1e-16f);
    float4 o0 = {av0.x * sinv, av0.y * sinv, av0.z * sinv, av0.w * sinv};
    float4 o1 = {av1.x * sinv, av1.y * sinv, av1.z * sinv, av1.w * sinv};
    float4 t0 = {at0.x * sinv, at0.y * sinv, at0.z * sinv, at0.w * sinv};
    float4 t1 = {at1.x * sinv, at1.y * sinv, at1.z * sinv, at1.w * sinv};
    *(float4*)&g_outv[node * HC + chan]     = o0;
    *(float4*)&g_outv[node * HC + chan + 4] = o1;
    *(float4*)&g_t   [node * HC + chan]     = t0;
    *(float4*)&g_t   [node * HC + chan + 4] = t1;
    if ((lane & 7) == 0) g_suma[node * 4 + h] = s * sinv;
}

// ---------------- epilogue 1: t@wedge + combine + LN + relu ---------------
__global__ void k_post(const float* __restrict__ wedge, const float* __restrict__ bedge,
                       const float* __restrict__ ln_g, const float* __restrict__ ln_b,
                       int n) {
    __shared__ float ts[16 * HC];
    __shared__ float os[16 * HC];
    int tid = threadIdx.x;
    int nb = blockIdx.x * 16;
    for (int i = tid; i < 1024; i += 256) {
        int row = i >> 6, q4 = i & 63;
        int node = nb + row;
        float4 v = make_float4(0.f, 0.f, 0.f, 0.f);
        if (node < n) v = *(const float4*)&g_t[node * HC + q4 * 4];
        *(float4*)&ts[row * HC + q4 * 4] = v;
    }
    __syncthreads();

    int warp = tid >> 5, lane = tid & 31;
    int row0 = (warp >> 2) * 8 + (lane >> 3) * 2;   // 2 rows
    int h    = warp & 3;
    int col0 = h * 64 + (lane & 7) * 8;

    u64 acc[2][4];
    #pragma unroll
    for (int rr = 0; rr < 2; rr++)
        #pragma unroll
        for (int jj = 0; jj < 4; jj++) acc[rr][jj] = 0ull;

    for (int i4 = 0; i4 < 64; i4 += 4) {
        float4 tv[2];
        #pragma unroll
        for (int rr = 0; rr < 2; rr++) tv[rr] = *(const float4*)&ts[(row0 + rr) * HC + h * 64 + i4];
        #pragma unroll
        for (int ii = 0; ii < 4; ii++) {
            const float* wrow = &wedge[(i4 + ii) * HC + col0];
            ulonglong2 wa = *(const ulonglong2*)wrow;
            ulonglong2 wb = *(const ulonglong2*)(wrow + 4);
            #pragma unroll
            for (int rr = 0; rr < 2; rr++) {
                float t = (ii == 0) ? tv[rr].x : (ii == 1) ? tv[rr].y : (ii == 2) ? tv[rr].z : tv[rr].w;
                u64 hh = pack2(t, t);
                acc[rr][0] = fma2(hh, wa.x, acc[rr][0]);
                acc[rr][1] = fma2(hh, wa.y, acc[rr][1]);
                acc[rr][2] = fma2(hh, wb.x, acc[rr][2]);
                acc[rr][3] = fma2(hh, wb.y, acc[rr][3]);
            }
        }
    }
    #pragma unroll
    for (int rr = 0; rr < 2; rr++) {
        int node = nb + row0 + rr;
        if (node < n) {
            float sa = g_suma[node * 4 + h];
            #pragma unroll
            for (int jj = 0; jj < 4; jj++) {
                int j = col0 + jj * 2;
                float2 f = unpack2(acc[rr][jj]);
                float2 ov = *(const float2*)&g_outv[node * HC + j];
                float2 sk = *(const float2*)&g_skip[node * HC + j];
                float2 be = *(const float2*)&bedge[j];
                f.x += ov.x + sa * be.x + sk.x;
                f.y += ov.y + sa * be.y + sk.y;
                *(float2*)&os[(row0 + rr) * HC + j] = f;
            }
        }
    }
    __syncthreads();

    int wid = warp;
    for (int m = wid; m < 16; m += 8) {
        int nn = nb + m;
        if (nn >= n) continue;
        float sum = 0.f, sq = 0.f;
        #pragma unroll
        for (int u = 0; u < 8; u++) {
            float v = os[m * HC + u * 32 + lane];
            sum += v; sq += v * v;
        }
        #pragma unroll
        for (int off = 16; off; off >>= 1) {
            sum += __shfl_xor_sync(0xffffffffu, sum, off);
            sq  += __shfl_xor_sync(0xffffffffu, sq,  off);
        }
        float mu = sum * (1.f / 256.f);
        float var = sq * (1.f / 256.f) - mu * mu;
        float rs = rsqrtf(var + 1e-5f);
        #pragma unroll
        for (int u = 0; u < 8; u++) {
            int j = u * 32 + lane;
            float v = (os[m * HC + j] - mu) * rs * __ldg(&ln_g[j]) + __ldg(&ln_b[j]);
            g_act[nn * HC + j] = fmaxf(v, 0.f);
        }
    }
}

// ---------------- epilogue 2: head MLP + log_softmax -----------------------
__global__ void k_head(const float* __restrict__ w1, const float* __restrict__ b1,
                       const float* __restrict__ w2, const float* __restrict__ b2,
                       float* __restrict__ out, int n) {
    __shared__ float as[16 * HC];
    __shared__ float hs[16 * 128];
    __shared__ float ls[16][NCLS];
    int tid = threadIdx.x;
    int nb = blockIdx.x * 16;
    for (int i = tid; i < 1024; i += 256) {
        int row = i >> 6, q4 = i & 63;
        int node = nb + row;
        float4 v = make_float4(0.f, 0.f, 0.f, 0.f);
        if (node < n) v = *(const float4*)&g_act[node * HC + q4 * 4];
        *(float4*)&as[row * HC + q4 * 4] = v;
    }
    __syncthreads();

    int rg = tid >> 4;             // 16 rows, 1 row per thread
    int col0 = (tid & 15) * 8;     // 8 cols

    u64 acc[4];
    #pragma unroll
    for (int jj = 0; jj < 4; jj++)
        acc[jj] = pack2(__ldg(&b1[col0 + jj * 2]), __ldg(&b1[col0 + jj * 2 + 1]));

    for (int i4 = 0; i4 < HC; i4 += 4) {
        float4 av = *(const float4*)&as[rg * HC + i4];
        #pragma unroll
        for (int ii = 0; ii < 4; ii++) {
            const float* wrow = &w1[(i4 + ii) * 128 + col0];
            ulonglong2 wa = *(const ulonglong2*)wrow;
            ulonglong2 wb = *(const ulonglong2*)(wrow + 4);
            float a = (ii == 0) ? av.x : (ii == 1) ? av.y : (ii == 2) ? av.z : av.w;
            u64 hh = pack2(a, a);
            acc[0] = fma2(hh, wa.x, acc[0]);
            acc[1] = fma2(hh, wa.y, acc[1]);
            acc[2] = fma2(hh, wb.x, acc[2]);
            acc[3] = fma2(hh, wb.y, acc[3]);
        }
    }
    #pragma unroll
    for (int jj = 0; jj < 4; jj++) {
        float2 f = unpack2(acc[jj]);
        *(float2*)&hs[rg * 128 + col0 + jj * 2] =
            make_float2(fmaxf(f.x, 0.f), fmaxf(f.y, 0.f));
    }
    __syncthreads();
    if (tid < 64) {
        int m = tid >> 2, c = tid & 3;
        float a = __ldg(&b2[c]);
        for (int i = 0; i < 128; i++) a += hs[m * 128 + i] * __ldg(&w2[i * NCLS + c]);
        ls[m][c] = a;
    }
    __syncthreads();
    if (tid < 16) {
        int nn = nb + tid;
        if (nn < n) {
            float l0 = ls[tid][0], l1 = ls[tid][1], l2 = ls[tid][2], l3 = ls[tid][3];
            float mx = fmaxf(fmaxf(l0, l1), fmaxf(l2, l3));
            float se = expf(l0 - mx) + expf(l1 - mx) + expf(l2 - mx) + expf(l3 - mx);
            float lse = mx + logf(se);
            out[nn * NCLS + 0] = l0 - lse;
            out[nn * NCLS + 1] = l1 - lse;
            out[nn * NCLS + 2] = l2 - lse;
            out[nn * NCLS + 3] = l3 - lse;
        }
    }
}

// ---------------- launcher ----------------
extern "C" void kernel_launch(void* const* d_in, const int* in_sizes, int n_in,
                              void* d_out, int out_size) {
    const float* x     = (const float*)d_in[0];
    const int*   ei    = (const int*)  d_in[1];
    const float* eattr = (const float*)d_in[2];
    const float* w00   = (const float*)d_in[3];
    const float* b00   = (const float*)d_in[4];
    const float* we1   = (const float*)d_in[5];
    const float* be1   = (const float*)d_in[6];
    const float* we2   = (const float*)d_in[7];
    const float* be2   = (const float*)d_in[8];
    const float* we3   = (const float*)d_in[9];
    const float* be3   = (const float*)d_in[10];
    const float* wq    = (const float*)d_in[11];
    const float* bq    = (const float*)d_in[12];
    const float* wk    = (const float*)d_in[13];
    const float* bk    = (const float*)d_in[14];
    const float* wv    = (const float*)d_in[15];
    const float* bv    = (const float*)d_in[16];
    const float* wedge = (const float*)d_in[17];
    const float* bedge = (const float*)d_in[18];
    const float* wskip = (const float*)d_in[19];
    const float* bskip = (const float*)d_in[20];
    const float* ln_g  = (const float*)d_in[21];
    const float* ln_b  = (const float*)d_in[22];
    const float* w1    = (const float*)d_in[23];
    const float* b1    = (const float*)d_in[24];
    const float* w2    = (const float*)d_in[25];
    const float* b2    = (const float*)d_in[26];
    float* out = (float*)d_out;

    int n = in_sizes[0] / NFEAT;
    int e = in_sizes[1] / 2;

    static const int EDGE_SMEM = (26112 * 4) + (128 * 4);   // 104960 bytes
    cudaFuncSetAttribute(k_edgemlp, cudaFuncAttributeMaxDynamicSharedMemorySize, EDGE_SMEM);

    k_zero_deg<<<(n + 255) / 256, 256>>>(n);
    k_hist<<<(e + 255) / 256, 256>>>(ei, e);
    k_scan<<<1, 1024>>>(n);
    k_scatter<<<(e + 255) / 256, 256>>>(ei, e);
    k_wtt<<<64, 256>>>(wedge);

    k_node_embed<<<(n + 63) / 64, 256>>>(x, w00, b00, n);
    {
        dim3 grid((n + 31) / 32, 4);
        k_proj<<<grid, 256>>>(wq, bq, wk, bk, wv, bv, wskip, bskip, n);
    }
    k_g<<<(n + 31) / 32, 256>>>(bedge, n);

    k_edgemlp<<<(e + 127) / 128, 256, EDGE_SMEM>>>(eattr, we1, be1, we2, be2, we3, be3, e);

    k_attn<<<(n + 7) / 8, 256>>>(n);

    k_post<<<(n + 15) / 16, 256>>>(wedge, bedge, ln_g, ln_b, n);
    k_head<<<(n + 15) / 16, 256>>>(w1, b1, w2, b2, out, n);
}

// round 4
// speedup vs baseline: 1.9986x; 1.9986x over previous
#include <cuda_runtime.h>
#include <math.h>

#define NFEAT 16
#define EFEAT 8
#define HC    256
#define NCLS  4

static const int MAXN = 50000;
static const int MAXE = 800000;

// ---------------- scratch ----------------
__device__ float g_x1  [MAXN * 64];
__device__ float g_q   [MAXN * HC];
__device__ float g_k   [MAXN * HC];
__device__ float g_v   [MAXN * HC];
__device__ float g_skip[MAXN * HC];
__device__ float g_g   [MAXN * HC];
__device__ float g_qb  [MAXN * 4];
__device__ float g_e   [MAXE * 64];
__device__ float g_outv[MAXN * HC];
__device__ float g_t   [MAXN * HC];
__device__ float g_suma[MAXN * 4];
__device__ float g_act [MAXN * HC];
__device__ int   g_deg [MAXN];
__device__ int   g_rowptr[MAXN + 1];
__device__ int   g_cursor[MAXN];
__device__ int   g_eid [MAXE];
__device__ int   g_src [MAXE];

// ---------------- CSR build ----------------
__global__ void k_zero_deg(int n) {
    int i = blockIdx.x * blockDim.x + threadIdx.x;
    if (i < n) g_deg[i] = 0;
}
__global__ void k_hist(const int* __restrict__ ei, int e) {
    int i = blockIdx.x * blockDim.x + threadIdx.x;
    if (i < e) atomicAdd(&g_deg[ei[e + i]], 1);
}
__global__ void k_scan(int n) {
    __shared__ int sh[1024];
    __shared__ int s_off;
    int tid = threadIdx.x;
    if (tid == 0) { s_off = 0; g_rowptr[0] = 0; }
    __syncthreads();
    for (int base = 0; base < n; base += 1024) {
        int i = base + tid;
        int val = (i < n) ? g_deg[i] : 0;
        sh[tid] = val;
        __syncthreads();
        for (int off = 1; off < 1024; off <<= 1) {
            int y = (tid >= off) ? sh[tid - off] : 0;
            __syncthreads();
            sh[tid] += y;
            __syncthreads();
        }
        int incl = sh[tid];
        if (i < n) {
            g_rowptr[i + 1] = s_off + incl;
            g_cursor[i]     = s_off + incl - val;
        }
        __syncthreads();
        if (tid == 0) s_off += sh[1023];
        __syncthreads();
    }
}
__global__ void k_scatter(const int* __restrict__ ei, int e) {
    int i = blockIdx.x * blockDim.x + threadIdx.x;
    if (i < e) {
        int dst = ei[e + i];
        int pos = atomicAdd(&g_cursor[dst], 1);
        g_eid[pos] = i;
        g_src[pos] = ei[i];
    }
}

// ---------------- node embed ----------------
__global__ void k_node_embed(const float* __restrict__ x,
                             const float* __restrict__ w00,
                             const float* __restrict__ b00, int n) {
    __shared__ float ws[NFEAT * 64];
    __shared__ float xs[64][NFEAT];
    int tid = threadIdx.x;
    for (int i = tid; i < NFEAT * 64; i += 256) ws[i] = w00[i];
    int nb = blockIdx.x * 64;
    for (int i = tid; i < 64 * NFEAT; i += 256) {
        int nn = nb + i / NFEAT;
        xs[i / NFEAT][i % NFEAT] = (nn < n) ? x[nn * NFEAT + (i % NFEAT)] : 0.f;
    }
    __syncthreads();
    int ln = tid >> 2;
    int node = nb + ln;
    int c0 = (tid & 3) * 16;
    if (node < n) {
        #pragma unroll
        for (int j = 0; j < 16; j++) {
            float acc = __ldg(&b00[c0 + j]);
            #pragma unroll
            for (int i = 0; i < NFEAT; i++) acc += xs[ln][i] * ws[i * 64 + c0 + j];
            g_x1[node * 64 + c0 + j] = fmaxf(acc, 0.f);
        }
    }
}

// ---------------- projections: warp-rowgroup layout, 64 nodes/block -------
__global__ void k_proj(const float* __restrict__ W0, const float* __restrict__ B0,
                       const float* __restrict__ W1, const float* __restrict__ B1,
                       const float* __restrict__ W2, const float* __restrict__ B2,
                       const float* __restrict__ W3, const float* __restrict__ B3,
                       int n) {
    int sel = blockIdx.y;
    const float* W = (sel == 0) ? W0 : (sel == 1) ? W1 : (sel == 2) ? W2 : W3;
    const float* B = (sel == 0) ? B0 : (sel == 1) ? B1 : (sel == 2) ? B2 : B3;
    float* out = (sel == 0) ? g_q : (sel == 1) ? g_k : (sel == 2) ? g_v : g_skip;

    __shared__ float xs[64 * 64];   // 16KB
    int tid = threadIdx.x;
    int nb = blockIdx.x * 64;
    for (int i = tid; i < 1024; i += 256) {
        int row = i >> 4, q4 = i & 15;
        int node = nb + row;
        float4 v = make_float4(0.f, 0.f, 0.f, 0.f);
        if (node < n) v = *(const float4*)&g_x1[node * 64 + q4 * 4];
        *(float4*)&xs[row * 64 + q4 * 4] = v;
    }
    __syncthreads();

    int warp = tid >> 5, lane = tid & 31;
    int row0 = warp * 8;       // 8 rows per warp (all lanes share)
    int col0 = lane * 8;       // 8 cols per lane

    float bcol[8];
    {
        float4 b0 = __ldg((const float4*)&B[col0]);
        float4 b1 = __ldg((const float4*)&B[col0 + 4]);
        bcol[0]=b0.x; bcol[1]=b0.y; bcol[2]=b0.z; bcol[3]=b0.w;
        bcol[4]=b1.x; bcol[5]=b1.y; bcol[6]=b1.z; bcol[7]=b1.w;
    }
    float acc[8][8];
    #pragma unroll
    for (int rr = 0; rr < 8; rr++)
        #pragma unroll
        for (int jj = 0; jj < 8; jj++) acc[rr][jj] = bcol[jj];

    for (int i4 = 0; i4 < 64; i4 += 4) {
        float4 xv[8];
        #pragma unroll
        for (int rr = 0; rr < 8; rr++)
            xv[rr] = *(const float4*)&xs[(row0 + rr) * 64 + i4];   // warp broadcast
        #pragma unroll
        for (int ii = 0; ii < 4; ii++) {
            float4 wa = __ldg((const float4*)&W[(i4 + ii) * HC + col0]);
            float4 wb = __ldg((const float4*)&W[(i4 + ii) * HC + col0 + 4]);
            #pragma unroll
            for (int rr = 0; rr < 8; rr++) {
                float h = (ii == 0) ? xv[rr].x : (ii == 1) ? xv[rr].y :
                          (ii == 2) ? xv[rr].z : xv[rr].w;
                acc[rr][0] += h * wa.x;  acc[rr][1] += h * wa.y;
                acc[rr][2] += h * wa.z;  acc[rr][3] += h * wa.w;
                acc[rr][4] += h * wb.x;  acc[rr][5] += h * wb.y;
                acc[rr][6] += h * wb.z;  acc[rr][7] += h * wb.w;
            }
        }
    }
    #pragma unroll
    for (int rr = 0; rr < 8; rr++) {
        int node = nb + row0 + rr;
        if (node < n) {
            float4 o0 = make_float4(acc[rr][0], acc[rr][1], acc[rr][2], acc[rr][3]);
            float4 o1 = make_float4(acc[rr][4], acc[rr][5], acc[rr][6], acc[rr][7]);
            *(float4*)&out[node * HC + col0]     = o0;
            *(float4*)&out[node * HC + col0 + 4] = o1;
        }
    }
}

// ---------------- g = per-head wedge^T @ q ; qb = q . bedge ----------------
__global__ void k_g(const float* __restrict__ wedge, const float* __restrict__ bedge,
                    int n) {
    __shared__ float qs[32 * HC];
    int tid = threadIdx.x;
    int nb = blockIdx.x * 32;
    for (int i = tid; i < 2048; i += 256) {
        int row = i >> 6, q4 = i & 63;
        int node = nb + row;
        float4 v = make_float4(0.f, 0.f, 0.f, 0.f);
        if (node < n) v = *(const float4*)&g_q[node * HC + q4 * 4];
        *(float4*)&qs[row * HC + q4 * 4] = v;
    }
    __syncthreads();
    int h = tid >> 6, ii = tid & 63;
    float acc[32];
    #pragma unroll
    for (int m = 0; m < 32; m++) acc[m] = 0.f;
    for (int c = 0; c < 64; c++) {
        float w = __ldg(&wedge[ii * HC + h * 64 + c]);
        #pragma unroll
        for (int m = 0; m < 32; m++) acc[m] += qs[m * HC + h * 64 + c] * w;
    }
    #pragma unroll
    for (int m = 0; m < 32; m++) {
        int nn = nb + m;
        if (nn < n) g_g[nn * HC + tid] = acc[m];
    }
    if (tid < 128) {
        int m = tid >> 2, h2 = tid & 3;
        int nn = nb + m;
        if (nn < n) {
            float s = 0.f;
            for (int c = 0; c < 64; c++) s += qs[m * HC + h2 * 64 + c] * __ldg(&bedge[h2 * 64 + c]);
            g_qb[nn * 4 + h2] = s;
        }
    }
}

// ---------------- edge MLP: 128 edges/block, warp-rowgroup broadcast ------
__global__ void k_edgemlp(const float* __restrict__ eattr,
                          const float* __restrict__ we1, const float* __restrict__ be1,
                          const float* __restrict__ we2, const float* __restrict__ be2,
                          const float* __restrict__ we3, const float* __restrict__ be3,
                          int e) {
    extern __shared__ float sm[];
    float* w1s = sm;                  // 512
    float* w2s = sm + 512;            // 4096
    float* w3s = sm + 4608;           // 4096
    float* es  = sm + 8704;           // 1024
    float* h1  = sm + 9728;           // 8192
    float* h2  = sm + 17920;          // 8192
    int*  eids = (int*)(sm + 26112);  // 128

    int tid = threadIdx.x;
    int pb = blockIdx.x * 128;
    for (int i = tid; i < 512; i += 256) w1s[i] = we1[i];
    for (int i = tid; i < 4096; i += 256) { w2s[i] = we2[i]; w3s[i] = we3[i]; }
    if (tid < 128) eids[tid] = (pb + tid < e) ? g_eid[pb + tid] : -1;
    __syncthreads();
    {
        int row = tid >> 1, half = tid & 1;
        int id = eids[row];
        float4 v = make_float4(0.f, 0.f, 0.f, 0.f);
        if (id >= 0) v = *(const float4*)&eattr[id * 8 + half * 4];
        *(float4*)&es[row * 8 + half * 4] = v;
    }
    __syncthreads();

    int warp = tid >> 5, lane = tid & 31;
    int row0 = warp * 16;     // 16 rows per warp
    int c2 = lane * 2;        // 2 cols per lane

    // ---- layer 1 (8 -> 64) ----
    {
        float acc[16][2];
        float b0 = w1s[0]; // dummy init to keep compiler calm
        float2 be = *(const float2*)&be1[c2];
        (void)b0;
        #pragma unroll
        for (int rr = 0; rr < 16; rr++) { acc[rr][0] = be.x; acc[rr][1] = be.y; }
        #pragma unroll
        for (int i = 0; i < 8; i++) {
            float2 w = *(const float2*)&w1s[i * 64 + c2];
            #pragma unroll
            for (int rr = 0; rr < 16; rr++) {
                float a = es[(row0 + rr) * 8 + i];   // broadcast
                acc[rr][0] += a * w.x;
                acc[rr][1] += a * w.y;
            }
        }
        #pragma unroll
        for (int rr = 0; rr < 16; rr++)
            *(float2*)&h1[(row0 + rr) * 64 + c2] =
                make_float2(fmaxf(acc[rr][0], 0.f), fmaxf(acc[rr][1], 0.f));
    }
    __syncthreads();

    // ---- layer 2 (64 -> 64) ----
    {
        float acc[16][2];
        float2 be = *(const float2*)&be2[c2];
        #pragma unroll
        for (int rr = 0; rr < 16; rr++) { acc[rr][0] = be.x; acc[rr][1] = be.y; }
        for (int i4 = 0; i4 < 16; i4++) {
            float2 w0 = *(const float2*)&w2s[(i4 * 4 + 0) * 64 + c2];
            float2 w1 = *(const float2*)&w2s[(i4 * 4 + 1) * 64 + c2];
            float2 w2v = *(const float2*)&w2s[(i4 * 4 + 2) * 64 + c2];
            float2 w3 = *(const float2*)&w2s[(i4 * 4 + 3) * 64 + c2];
            #pragma unroll
            for (int rr = 0; rr < 16; rr++) {
                float4 hv = *(const float4*)&h1[(row0 + rr) * 64 + i4 * 4]; // broadcast
                acc[rr][0] += hv.x * w0.x + hv.y * w1.x + hv.z * w2v.x + hv.w * w3.x;
                acc[rr][1] += hv.x * w0.y + hv.y * w1.y + hv.z * w2v.y + hv.w * w3.y;
            }
        }
        __syncthreads();
        #pragma unroll
        for (int rr = 0; rr < 16; rr++)
            *(float2*)&h2[(row0 + rr) * 64 + c2] =
                make_float2(fmaxf(acc[rr][0], 0.f), fmaxf(acc[rr][1], 0.f));
    }
    __syncthreads();

    // ---- layer 3 (64 -> 64) -> g_e ----
    {
        float acc[16][2];
        float2 be = *(const float2*)&be3[c2];
        #pragma unroll
        for (int rr = 0; rr < 16; rr++) { acc[rr][0] = be.x; acc[rr][1] = be.y; }
        for (int i4 = 0; i4 < 16; i4++) {
            float2 w0 = *(const float2*)&w3s[(i4 * 4 + 0) * 64 + c2];
            float2 w1 = *(const float2*)&w3s[(i4 * 4 + 1) * 64 + c2];
            float2 w2v = *(const float2*)&w3s[(i4 * 4 + 2) * 64 + c2];
            float2 w3 = *(const float2*)&w3s[(i4 * 4 + 3) * 64 + c2];
            #pragma unroll
            for (int rr = 0; rr < 16; rr++) {
                float4 hv = *(const float4*)&h2[(row0 + rr) * 64 + i4 * 4]; // broadcast
                acc[rr][0] += hv.x * w0.x + hv.y * w1.x + hv.z * w2v.x + hv.w * w3.x;
                acc[rr][1] += hv.x * w0.y + hv.y * w1.y + hv.z * w2v.y + hv.w * w3.y;
            }
        }
        #pragma unroll
        for (int rr = 0; rr < 16; rr++) {
            int p = pb + row0 + rr;
            if (p < e)
                *(float2*)&g_e[p * 64 + c2] =
                    make_float2(fmaxf(acc[rr][0], 0.f), fmaxf(acc[rr][1], 0.f));
        }
    }
}

// ---------------- attention: warp per node, 8-lane head groups -------------
__device__ __forceinline__ float dot4(float4 a, float4 b) {
    return a.x * b.x + a.y * b.y + a.z * b.z + a.w * b.w;
}

__global__ void k_attn(int n) {
    int gw = (blockIdx.x * blockDim.x + threadIdx.x) >> 5;
    int lane = threadIdx.x & 31;
    if (gw >= n) return;
    int node = gw;
    int beg = g_rowptr[node], end = g_rowptr[node + 1];

    int h = lane >> 3;
    int c8 = (lane & 7) * 8;
    int chan = h * 64 + c8;

    float4 q0 = *(const float4*)&g_q[node * HC + chan];
    float4 q1 = *(const float4*)&g_q[node * HC + chan + 4];
    float4 gg0 = *(const float4*)&g_g[node * HC + chan];
    float4 gg1 = *(const float4*)&g_g[node * HC + chan + 4];
    float qb = g_qb[node * 4 + h];

    float s = 0.f;
    float4 av0 = {0,0,0,0}, av1 = {0,0,0,0};
    float4 at0 = {0,0,0,0}, at1 = {0,0,0,0};

    int p = beg;
    for (; p + 2 <= end; p += 2) {
        int srcA = g_src[p], srcB = g_src[p + 1];
        float4 kA0 = *(const float4*)&g_k[srcA * HC + chan];
        float4 kA1 = *(const float4*)&g_k[srcA * HC + chan + 4];
        float4 eA0 = *(const float4*)&g_e[p * 64 + c8];
        float4 eA1 = *(const float4*)&g_e[p * 64 + c8 + 4];
        float4 kB0 = *(const float4*)&g_k[srcB * HC + chan];
        float4 kB1 = *(const float4*)&g_k[srcB * HC + chan + 4];
        float4 eB0 = *(const float4*)&g_e[(p + 1) * 64 + c8];
        float4 eB1 = *(const float4*)&g_e[(p + 1) * 64 + c8 + 4];

        float dA = dot4(q0, kA0) + dot4(q1, kA1) + dot4(gg0, eA0) + dot4(gg1, eA1);
        float dB = dot4(q0, kB0) + dot4(q1, kB1) + dot4(gg0, eB0) + dot4(gg1, eB1);
        dA += __shfl_xor_sync(0xffffffffu, dA, 1);
        dB += __shfl_xor_sync(0xffffffffu, dB, 1);
        dA += __shfl_xor_sync(0xffffffffu, dA, 2);
        dB += __shfl_xor_sync(0xffffffffu, dB, 2);
        dA += __shfl_xor_sync(0xffffffffu, dA, 4);
        dB += __shfl_xor_sync(0xffffffffu, dB, 4);
        float peA = __expf((dA + qb) * 0.125f);
        float peB = __expf((dB + qb) * 0.125f);
        s += peA + peB;

        float4 vA0 = *(const float4*)&g_v[srcA * HC + chan];
        float4 vA1 = *(const float4*)&g_v[srcA * HC + chan + 4];
        float4 vB0 = *(const float4*)&g_v[srcB * HC + chan];
        float4 vB1 = *(const float4*)&g_v[srcB * HC + chan + 4];

        av0.x += peA * vA0.x + peB * vB0.x;  av0.y += peA * vA0.y + peB * vB0.y;
        av0.z += peA * vA0.z + peB * vB0.z;  av0.w += peA * vA0.w + peB * vB0.w;
        av1.x += peA * vA1.x + peB * vB1.x;  av1.y += peA * vA1.y + peB * vB1.y;
        av1.z += peA * vA1.z + peB * vB1.z;  av1.w += peA * vA1.w + peB * vB1.w;
        at0.x += peA * eA0.x + peB * eB0.x;  at0.y += peA * eA0.y + peB * eB0.y;
        at0.z += peA * eA0.z + peB * eB0.z;  at0.w += peA * eA0.w + peB * eB0.w;
        at1.x += peA * eA1.x + peB * eB1.x;  at1.y += peA * eA1.y + peB * eB1.y;
        at1.z += peA * eA1.z + peB * eB1.z;  at1.w += peA * eA1.w + peB * eB1.w;
    }
    if (p < end) {
        int src = g_src[p];
        float4 k0 = *(const float4*)&g_k[src * HC + chan];
        float4 k1 = *(const float4*)&g_k[src * HC + chan + 4];
        float4 e0 = *(const float4*)&g_e[p * 64 + c8];
        float4 e1 = *(const float4*)&g_e[p * 64 + c8 + 4];
        float d = dot4(q0, k0) + dot4(q1, k1) + dot4(gg0, e0) + dot4(gg1, e1);
        d += __shfl_xor_sync(0xffffffffu, d, 1);
        d += __shfl_xor_sync(0xffffffffu, d, 2);
        d += __shfl_xor_sync(0xffffffffu, d, 4);
        float pe = __expf((d + qb) * 0.125f);
        s += pe;
        float4 v0 = *(const float4*)&g_v[src * HC + chan];
        float4 v1 = *(const float4*)&g_v[src * HC + chan + 4];
        av0.x += pe * v0.x; av0.y += pe * v0.y; av0.z += pe * v0.z; av0.w += pe * v0.w;
        av1.x += pe * v1.x; av1.y += pe * v1.y; av1.z += pe * v1.z; av1.w += pe * v1.w;
        at0.x += pe * e0.x; at0.y += pe * e0.y; at0.z += pe * e0.z; at0.w += pe * e0.w;
        at1.x += pe * e1.x; at1.y += pe * e1.y; at1.z += pe * e1.z; at1.w += pe * e1.w;
    }

    float sinv = 1.f / (s + 1e-16f);
    float4 o0 = {av0.x * sinv, av0.y * sinv, av0.z * sinv, av0.w * sinv};
    float4 o1 = {av1.x * sinv, av1.y * sinv, av1.z * sinv, av1.w * sinv};
    float4 t0 = {at0.x * sinv, at0.y * sinv, at0.z * sinv, at0.w * sinv};
    float4 t1 = {at1.x * sinv, at1.y * sinv, at1.z * sinv, at1.w * sinv};
    *(float4*)&g_outv[node * HC + chan]     = o0;
    *(float4*)&g_outv[node * HC + chan + 4] = o1;
    *(float4*)&g_t   [node * HC + chan]     = t0;
    *(float4*)&g_t   [node * HC + chan + 4] = t1;
    if ((lane & 7) == 0) g_suma[node * 4 + h] = s * sinv;
}

// ---------------- epilogue 1 ----------------
__global__ void k_post(const float* __restrict__ wedge, const float* __restrict__ bedge,
                       const float* __restrict__ ln_g, const float* __restrict__ ln_b,
                       int n) {
    __shared__ float ts[16][HC];
    __shared__ float os[16][HC];
    int tid = threadIdx.x;
    int nb = blockIdx.x * 16;
    for (int i = tid; i < 16 * HC; i += 256) {
        int nn = nb + i / HC;
        ts[i / HC][i % HC] = (nn < n) ? g_t[nn * HC + (i % HC)] : 0.f;
    }
    __syncthreads();
    int h = tid >> 6;
    float acc[16];
    #pragma unroll
    for (int m = 0; m < 16; m++) acc[m] = 0.f;
    for (int i = 0; i < 64; i++) {
        float w = __ldg(&wedge[i * HC + tid]);
        #pragma unroll
        for (int m = 0; m < 16; m++) acc[m] += ts[m][h * 64 + i] * w;
    }
    float be = __ldg(&bedge[tid]);
    #pragma unroll
    for (int m = 0; m < 16; m++) {
        int nn = nb + m;
        if (nn < n) {
            float val = g_outv[nn * HC + tid] + g_suma[nn * 4 + h] * be
                      + g_skip[nn * HC + tid] + acc[m];
            os[m][tid] = val;
        }
    }
    __syncthreads();
    int wid = tid >> 5, lane = tid & 31;
    for (int m = wid; m < 16; m += 8) {
        int nn = nb + m;
        if (nn >= n) continue;
        float sum = 0.f, sq = 0.f;
        #pragma unroll
        for (int u = 0; u < 8; u++) {
            float v = os[m][u * 32 + lane];
            sum += v; sq += v * v;
        }
        #pragma unroll
        for (int off = 16; off; off >>= 1) {
            sum += __shfl_xor_sync(0xffffffffu, sum, off);
            sq  += __shfl_xor_sync(0xffffffffu, sq,  off);
        }
        float mu = sum * (1.f / 256.f);
        float var = sq * (1.f / 256.f) - mu * mu;
        float rs = rsqrtf(var + 1e-5f);
        #pragma unroll
        for (int u = 0; u < 8; u++) {
            int j = u * 32 + lane;
            float v = (os[m][j] - mu) * rs * __ldg(&ln_g[j]) + __ldg(&ln_b[j]);
            g_act[nn * HC + j] = fmaxf(v, 0.f);
        }
    }
}

// ---------------- epilogue 2 ----------------
__global__ void k_head(const float* __restrict__ w1, const float* __restrict__ b1,
                       const float* __restrict__ w2, const float* __restrict__ b2,
                       float* __restrict__ out, int n) {
    __shared__ float as[16][HC];
    __shared__ float hs[16][128];
    __shared__ float ls[16][NCLS];
    int tid = threadIdx.x;
    int nb = blockIdx.x * 16;
    for (int i = tid; i < 16 * HC; i += 128) {
        int nn = nb + i / HC;
        as[i / HC][i % HC] = (nn < n) ? g_act[nn * HC + (i % HC)] : 0.f;
    }
    __syncthreads();
    float acc[16];
    float bb = __ldg(&b1[tid]);
    #pragma unroll
    for (int m = 0; m < 16; m++) acc[m] = bb;
    for (int i = 0; i < HC; i++) {
        float w = __ldg(&w1[i * 128 + tid]);
        #pragma unroll
        for (int m = 0; m < 16; m++) acc[m] += as[m][i] * w;
    }
    #pragma unroll
    for (int m = 0; m < 16; m++) hs[m][tid] = fmaxf(acc[m], 0.f);
    __syncthreads();
    if (tid < 64) {
        int m = tid >> 2, c = tid & 3;
        float a = __ldg(&b2[c]);
        for (int i = 0; i < 128; i++) a += hs[m][i] * __ldg(&w2[i * NCLS + c]);
        ls[m][c] = a;
    }
    __syncthreads();
    if (tid < 16) {
        int nn = nb + tid;
        if (nn < n) {
            float l0 = ls[tid][0], l1 = ls[tid][1], l2 = ls[tid][2], l3 = ls[tid][3];
            float mx = fmaxf(fmaxf(l0, l1), fmaxf(l2, l3));
            float se = expf(l0 - mx) + expf(l1 - mx) + expf(l2 - mx) + expf(l3 - mx);
            float lse = mx + logf(se);
            out[nn * NCLS + 0] = l0 - lse;
            out[nn * NCLS + 1] = l1 - lse;
            out[nn * NCLS + 2] = l2 - lse;
            out[nn * NCLS + 3] = l3 - lse;
        }
    }
}

// ---------------- launcher ----------------
extern "C" void kernel_launch(void* const* d_in, const int* in_sizes, int n_in,
                              void* d_out, int out_size) {
    const float* x     = (const float*)d_in[0];
    const int*   ei    = (const int*)  d_in[1];
    const float* eattr = (const float*)d_in[2];
    const float* w00   = (const float*)d_in[3];
    const float* b00   = (const float*)d_in[4];
    const float* we1   = (const float*)d_in[5];
    const float* be1   = (const float*)d_in[6];
    const float* we2   = (const float*)d_in[7];
    const float* be2   = (const float*)d_in[8];
    const float* we3   = (const float*)d_in[9];
    const float* be3   = (const float*)d_in[10];
    const float* wq    = (const float*)d_in[11];
    const float* bq    = (const float*)d_in[12];
    const float* wk    = (const float*)d_in[13];
    const float* bk    = (const float*)d_in[14];
    const float* wv    = (const float*)d_in[15];
    const float* bv    = (const float*)d_in[16];
    const float* wedge = (const float*)d_in[17];
    const float* bedge = (const float*)d_in[18];
    const float* wskip = (const float*)d_in[19];
    const float* bskip = (const float*)d_in[20];
    const float* ln_g  = (const float*)d_in[21];
    const float* ln_b  = (const float*)d_in[22];
    const float* w1    = (const float*)d_in[23];
    const float* b1    = (const float*)d_in[24];
    const float* w2    = (const float*)d_in[25];
    const float* b2    = (const float*)d_in[26];
    float* out = (float*)d_out;

    int n = in_sizes[0] / NFEAT;
    int e = in_sizes[1] / 2;

    static const int EDGE_SMEM = (26112 * 4) + (128 * 4);   // 104960 bytes
    cudaFuncSetAttribute(k_edgemlp, cudaFuncAttributeMaxDynamicSharedMemorySize, EDGE_SMEM);

    k_zero_deg<<<(n + 255) / 256, 256>>>(n);
    k_hist<<<(e + 255) / 256, 256>>>(ei, e);
    k_scan<<<1, 1024>>>(n);
    k_scatter<<<(e + 255) / 256, 256>>>(ei, e);

    k_node_embed<<<(n + 63) / 64, 256>>>(x, w00, b00, n);
    {
        dim3 grid((n + 63) / 64, 4);
        k_proj<<<grid, 256>>>(wq, bq, wk, bk, wv, bv, wskip, bskip, n);
    }
    k_g<<<(n + 31) / 32, 256>>>(wedge, bedge, n);

    k_edgemlp<<<(e + 127) / 128, 256, EDGE_SMEM>>>(eattr, we1, be1, we2, be2, we3, be3, e);

    k_attn<<<(n + 7) / 8, 256>>>(n);

    k_post<<<(n + 15) / 16, 256>>>(wedge, bedge, ln_g, ln_b, n);
    k_head<<<(n + 15) / 16, 128>>>(w1, b1, w2, b2, out, n);
}